// round 14
// baseline (speedup 1.0000x reference)
#include <cuda_runtime.h>
#include <math.h>

#define NUM_PINS 4194304
#define NUM_NETS 524288
#define NETS_PER_WIN 128
#define NWIN (NUM_NETS / NETS_PER_WIN)   // 4096
#define NBLK 740                          // 5 blocks/SM * 148 SMs, persistent
#define TB 128
#define CAP 1280   // staged floats per stream per buffer; window span ~N(1024,32^2)+3 -> ~8 sigma
#define GL 0.36067376022224085f   // 0.25 * log2(e)

// CSR row pointers: S[n] = first pin of net n, S[NUM_NETS] = NUM_PINS.
__device__ int g_S[NUM_NETS + 1];
__device__ float    g_acc;    // zero at load; self-resetting each launch
__device__ unsigned g_done;

// ---- f32x2 packed helpers (sm_100a) ----
typedef unsigned long long u64;
__device__ __forceinline__ u64 pk2(float lo, float hi) {
    u64 r; asm("mov.b64 %0, {%1,%2};" : "=l"(r) : "f"(lo), "f"(hi)); return r;
}
__device__ __forceinline__ void up2(u64 v, float& lo, float& hi) {
    asm("mov.b64 {%0,%1}, %2;" : "=f"(lo), "=f"(hi) : "l"(v));
}
#define FMA2(d,a,b,c) asm("fma.rn.f32x2 %0, %1, %2, %3;" : "=l"(d) : "l"(a), "l"(b), "l"(c))
#define ADD2(d,a,b)   asm("add.rn.f32x2 %0, %1, %2;"     : "=l"(d) : "l"(a), "l"(b))
__device__ __forceinline__ float ex2a(float a) {
    float r; asm("ex2.approx.f32 %0, %1;" : "=f"(r) : "f"(a)); return r;
}
__device__ __forceinline__ unsigned smem_u32(const void* p) {
    return (unsigned)__cvta_generic_to_shared(p);
}
#define CPA16(dst, src) \
    asm volatile("cp.async.cg.shared.global [%0], [%1], 16;" :: "r"(dst), "l"(src) : "memory")

// Build CSR row pointers from the SORTED pin2net_map (R12 version).
__global__ void csr_kernel(const int* __restrict__ seg) {
    const int i4 = blockIdx.x * blockDim.x + threadIdx.x;
    if (i4 >= NUM_PINS / 4) return;
    const int base = i4 * 4;
    const int4 v = ((const int4*)seg)[i4];
    int prv = __shfl_up_sync(0xffffffffu, v.w, 1);
    if ((threadIdx.x & 31) == 0)
        prv = (base > 0) ? __ldg(seg + base - 1) : -1;
    for (int m = prv + 1; m <= v.x; m++) g_S[m] = base;
    for (int m = v.x + 1; m <= v.y; m++) g_S[m] = base + 1;
    for (int m = v.y + 1; m <= v.z; m++) g_S[m] = base + 2;
    for (int m = v.z + 1; m <= v.w; m++) g_S[m] = base + 3;
    if (base + 4 == NUM_PINS) {
        for (int m = v.w + 1; m <= NUM_NETS; m++) g_S[m] = NUM_PINS;
    }
}

// Persistent double-buffered kernel: each block walks windows w, w+NBLK, ...
// Window w+NBLK's 4 data streams are cp.async'd while window w is sorted and
// computed. Hot loops are smem-only; global fallback loops cover span>CAP.
__global__ void __launch_bounds__(TB, 5) per_net_kernel(
    const float* __restrict__ X,
    const float* __restrict__ Y,
    const float* __restrict__ DX,
    const float* __restrict__ DY,
    const float* __restrict__ W,
    float* __restrict__ out)
{
    __shared__ float SX[2][CAP], SY[2][CAP], SDX[2][CAP], SDY[2][CAP];
    __shared__ unsigned short s_sst[NETS_PER_WIN];
    __shared__ unsigned short s_sen[NETS_PER_WIN];
    __shared__ unsigned char  s_nid[NETS_PER_WIN];
    __shared__ int s_hist[32], s_offs[32];
    __shared__ float swarp[4];

    const int tid  = threadIdx.x;
    const int lane = tid & 31, wid = tid >> 5;
    float contrib = 0.0f;

    // ---- prologue: stage first window into buffer 0 ----
    {
        const int base  = blockIdx.x * NETS_PER_WIN;
        const int pinlo = __ldg(g_S + base);
        const int pinhi = __ldg(g_S + base + NETS_PER_WIN);
        const int alo   = pinlo & ~3;
        const int spanF = pinhi - alo;
        const int limF  = ((spanF + 3) & ~3) < CAP ? ((spanF + 3) & ~3) : CAP;
        for (int i = tid * 4; i < limF; i += TB * 4) {
            const int g = alo + i;
            CPA16(smem_u32(&SX[0][i]),  X  + g);
            CPA16(smem_u32(&SY[0][i]),  Y  + g);
            CPA16(smem_u32(&SDX[0][i]), DX + g);
            CPA16(smem_u32(&SDY[0][i]), DY + g);
        }
    }
    asm volatile("cp.async.commit_group;" ::: "memory");

    int parity = 0;
    for (int w = blockIdx.x; w < NWIN; w += NBLK, parity ^= 1) {
        if (tid < 32) s_hist[tid] = 0;

        // ---- prefetch next window into the other buffer ----
        const int wn = w + NBLK;
        if (wn < NWIN) {
            const int nb    = wn * NETS_PER_WIN;
            const int plo   = __ldg(g_S + nb);
            const int phi   = __ldg(g_S + nb + NETS_PER_WIN);
            const int nalo  = plo & ~3;
            const int nspan = phi - nalo;
            const int nlim  = ((nspan + 3) & ~3) < CAP ? ((nspan + 3) & ~3) : CAP;
            const int bp    = parity ^ 1;
            for (int i = tid * 4; i < nlim; i += TB * 4) {
                const int g = nalo + i;
                CPA16(smem_u32(&SX[bp][i]),  X  + g);
                CPA16(smem_u32(&SY[bp][i]),  Y  + g);
                CPA16(smem_u32(&SDX[bp][i]), DX + g);
                CPA16(smem_u32(&SDY[bp][i]), DY + g);
            }
        }
        asm volatile("cp.async.commit_group;" ::: "memory");  // exactly 1 group/iter

        // ---- metadata + counting sort for window w (overlaps the copies) ----
        const int base  = w * NETS_PER_WIN;
        const int st0   = __ldg(g_S + base + tid);
        const int en0   = __ldg(g_S + base + tid + 1);
        const int pinlo = __ldg(g_S + base);
        const int alo   = pinlo & ~3;
        const int sz0   = en0 - st0;

        __syncthreads();                      // hist zeros visible
        const int bin  = sz0 < 31 ? sz0 : 31;
        const int rank = atomicAdd(&s_hist[bin], 1);
        __syncthreads();
        if (tid < 32) {
            int c = s_hist[tid];
            int v = c;
            #pragma unroll
            for (int off = 1; off < 32; off <<= 1) {
                int u = __shfl_up_sync(0xffffffffu, v, off);
                if (tid >= off) v += u;
            }
            s_offs[tid] = v - c;
        }
        __syncthreads();
        const int pos = s_offs[bin] + rank;
        s_sst[pos] = (unsigned short)(st0 - alo);
        s_sen[pos] = (unsigned short)(en0 - alo);
        s_nid[pos] = (unsigned char)tid;

        asm volatile("cp.async.wait_group 1;" ::: "memory");  // window w data ready
        __syncthreads();                       // staging + scatter visible

        const int js  = s_sst[tid];
        const int je  = s_sen[tid];
        const int nid = s_nid[tid];
        const float* SXb  = SX[parity];
        const float* SYb  = SY[parity];
        const float* SDXb = SDX[parity];
        const float* SDYb = SDY[parity];

        const int cn = je - js;
        if (cn > 1) {   // cnt<=1 nets contribute exactly 0
            const float wgt = __ldg(W + base + nid);

            const int jeH = je < CAP ? je : CAP;
            const int jcS = js > CAP ? js : CAP;

            // ---- Pass 1: max/min/sum ----
            float xmax = -3.402823466e38f, xmin = 3.402823466e38f;
            float ymax = -3.402823466e38f, ymin = 3.402823466e38f;
            u64 sum2 = pk2(0.0f, 0.0f);
            #pragma unroll 2
            for (int j = js; j < jeH; j++) {
                float px = SXb[j], py = SYb[j];
                xmax = fmaxf(xmax, px); xmin = fminf(xmin, px);
                ymax = fmaxf(ymax, py); ymin = fminf(ymin, py);
                u64 t; asm("mov.b64 %0, {%1,%2};" : "=l"(t) : "f"(px), "f"(py));
                ADD2(sum2, sum2, t);
            }
            for (int j = jcS; j < je; j++) {       // normally zero trips
                float px = __ldg(X + alo + j), py = __ldg(Y + alo + j);
                xmax = fmaxf(xmax, px); xmin = fminf(xmin, px);
                ymax = fmaxf(ymax, py); ymin = fminf(ymin, py);
                u64 t = pk2(px, py);
                ADD2(sum2, sum2, t);
            }
            float sumx, sumy; up2(sum2, sumx, sumy);

            const float rc = __fdividef(1.0f, (float)cn);
            const float cx = sumx * rc;
            const float cy = sumy * rc;

            // ---- Pass 2: packed WA sums + direction penalty ----
            const u64 g2    = pk2(GL, GL);
            const u64 ng2   = pk2(-GL, -GL);
            const u64 cmaxg = pk2(-xmax * GL, -ymax * GL);
            const u64 cming = pk2(xmin * GL, ymin * GL);
            const u64 c2    = pk2(cx, cy);
            const u64 none2 = pk2(-1.0f, -1.0f);
            const u64 onec  = pk2(1.0f, 1.0f);
            u64 se2 = pk2(0.f, 0.f), sve2 = pk2(0.f, 0.f);
            u64 sm2 = pk2(0.f, 0.f), svm2 = pk2(0.f, 0.f);
            float pen = 0.f;

            #pragma unroll 2
            for (int j = js; j < jeH; j++) {
                float px = SXb[j],  py  = SYb[j];
                float ddx = SDXb[j], ddy = SDYb[j];
                u64 t; asm("mov.b64 %0, {%1,%2};" : "=l"(t) : "f"(px), "f"(py));

                u64 argp, argm;
                FMA2(argp, t, g2,  cmaxg);
                FMA2(argm, t, ng2, cming);
                float apx, apy, amx, amy;
                up2(argp, apx, apy);
                up2(argm, amx, amy);
                u64 ep2 = pk2(ex2a(apx), ex2a(apy));
                u64 em2 = pk2(ex2a(amx), ex2a(amy));

                FMA2(se2,  ep2, onec, se2);
                FMA2(sve2, t,   ep2,  sve2);
                FMA2(sm2,  em2, onec, sm2);
                FMA2(svm2, t,   em2,  svm2);

                u64 dd2;
                FMA2(dd2, t, none2, c2);
                float dxp, dyp;
                up2(dd2, dxp, dyp);
                float r2  = fmaxf(fmaf(dxp, dxp, dyp * dyp), 1e-16f);
                float dot = fmaf(dxp, ddx, dyp * ddy);
                float cc  = dot * rsqrtf(r2);
                pen += fmaxf(0.5f - cc, 0.0f);
            }
            for (int j = jcS; j < je; j++) {       // normally zero trips
                float px = __ldg(X + alo + j),  py  = __ldg(Y + alo + j);
                float ddx = __ldg(DX + alo + j), ddy = __ldg(DY + alo + j);
                u64 t = pk2(px, py);

                u64 argp, argm;
                FMA2(argp, t, g2,  cmaxg);
                FMA2(argm, t, ng2, cming);
                float apx, apy, amx, amy;
                up2(argp, apx, apy);
                up2(argm, amx, amy);
                u64 ep2 = pk2(ex2a(apx), ex2a(apy));
                u64 em2 = pk2(ex2a(amx), ex2a(amy));

                FMA2(se2,  ep2, onec, se2);
                FMA2(sve2, t,   ep2,  sve2);
                FMA2(sm2,  em2, onec, sm2);
                FMA2(svm2, t,   em2,  svm2);

                u64 dd2;
                FMA2(dd2, t, none2, c2);
                float dxp, dyp;
                up2(dd2, dxp, dyp);
                float r2  = fmaxf(fmaf(dxp, dxp, dyp * dyp), 1e-16f);
                float dot = fmaf(dxp, ddx, dyp * ddy);
                float cc  = dot * rsqrtf(r2);
                pen += fmaxf(0.5f - cc, 0.0f);
            }

            float sex, sey, svex, svey, smx, smy, svmx, svmy;
            up2(se2, sex, sey);   up2(sve2, svex, svey);
            up2(sm2, smx, smy);   up2(svm2, svmx, svmy);

            // se/sm >= 1 always: no eps guards.
            float wax = __fdividef(svex, sex) - __fdividef(svmx, smx);
            float way = __fdividef(svey, sey) - __fdividef(svmy, smy);
            float wl  = fmaxf(wax + way, 0.0f);    // ALPHA == 1.0
            contrib += wgt * (1.0f + pen * rc) * wl;   // net_mask == 1
        }
        __syncthreads();   // all reads of buffers/metadata done before next iter
    }

    // ---- block reduction, then global last-block reduction ----
    float v = contrib;
    #pragma unroll
    for (int off = 16; off > 0; off >>= 1)
        v += __shfl_down_sync(0xffffffffu, v, off);
    if (lane == 0) swarp[wid] = v;
    __syncthreads();
    if (tid == 0) {
        v = swarp[0] + swarp[1] + swarp[2] + swarp[3];
        atomicAdd(&g_acc, v);
        __threadfence();
        unsigned t = atomicAdd(&g_done, 1u);
        if (t == NBLK - 1) {
            out[0] = atomicExch(&g_acc, 0.0f);   // final sum; reset for next replay
            g_done = 0;
            __threadfence();
        }
    }
}

extern "C" void kernel_launch(void* const* d_in, const int* in_sizes, int n_in,
                              void* d_out, int out_size)
{
    const float* pos  = (const float*)d_in[0];   // 2*P floats: x then y
    const float* dirx = (const float*)d_in[1];
    const float* diry = (const float*)d_in[2];
    const float* w    = (const float*)d_in[3];
    const int*   seg  = (const int*)d_in[4];
    float* out = (float*)d_out;

    csr_kernel<<<(NUM_PINS / 4 + 255) / 256, 256>>>(seg);

    per_net_kernel<<<NBLK, TB>>>(pos, pos + NUM_PINS, dirx, diry, w, out);
}

// round 15
// speedup vs baseline: 1.1260x; 1.1260x over previous
#include <cuda_runtime.h>
#include <math.h>

#define NUM_PINS 4194304
#define NUM_NETS 524288
#define NETS_PER_BLOCK 128
#define TB 128
#define CAP 1280   // staged floats per stream; block span ~N(1024,32^2)+3 -> ~8 sigma; fallback loops cover overflow
#define GL 0.36067376022224085f   // 0.25 * log2(e): exp(z/4) = ex2(z*GL)

// CSR row pointers: S[n] = first pin of net n, S[NUM_NETS] = NUM_PINS.
__device__ int g_S[NUM_NETS + 1];

// ---- f32x2 packed helpers (sm_100a) ----
typedef unsigned long long u64;
__device__ __forceinline__ u64 pk2(float lo, float hi) {
    u64 r; asm("mov.b64 %0, {%1,%2};" : "=l"(r) : "f"(lo), "f"(hi)); return r;
}
__device__ __forceinline__ void up2(u64 v, float& lo, float& hi) {
    asm("mov.b64 {%0,%1}, %2;" : "=f"(lo), "=f"(hi) : "l"(v));
}
#define FMA2(d,a,b,c) asm("fma.rn.f32x2 %0, %1, %2, %3;" : "=l"(d) : "l"(a), "l"(b), "l"(c))
#define ADD2(d,a,b)   asm("add.rn.f32x2 %0, %1, %2;"     : "=l"(d) : "l"(a), "l"(b))
__device__ __forceinline__ float ex2a(float a) {
    float r; asm("ex2.approx.f32 %0, %1;" : "=f"(r) : "f"(a)); return r;
}
__device__ __forceinline__ unsigned smem_u32(const void* p) {
    return (unsigned)__cvta_generic_to_shared(p);
}
#define CPA16(dst, src) \
    asm volatile("cp.async.cg.shared.global [%0], [%1], 16;" :: "r"(dst), "l"(src) : "memory")

// Build CSR row pointers from the SORTED pin2net_map; 8 elements per thread.
// Also zeroes out[0]. Neighbor comes from the previous lane via shuffle.
__global__ void csr_kernel(const int* __restrict__ seg, float* __restrict__ out) {
    const int i8 = blockIdx.x * blockDim.x + threadIdx.x;
    if (i8 == 0) out[0] = 0.0f;
    if (i8 >= NUM_PINS / 8) return;
    const int base = i8 * 8;
    const int4 a = ((const int4*)seg)[i8 * 2];
    const int4 b = ((const int4*)seg)[i8 * 2 + 1];

    // previous element: lanes 1-31 take it from lane-1's b.w; lane 0 loads.
    int prv = __shfl_up_sync(0xffffffffu, b.w, 1);
    if ((threadIdx.x & 31) == 0)
        prv = (base > 0) ? __ldg(seg + base - 1) : -1;

    // common path: each boundary writes one entry; empty-net gaps loop (rare).
    for (int m = prv + 1; m <= a.x; m++) g_S[m] = base;
    for (int m = a.x + 1; m <= a.y; m++) g_S[m] = base + 1;
    for (int m = a.y + 1; m <= a.z; m++) g_S[m] = base + 2;
    for (int m = a.z + 1; m <= a.w; m++) g_S[m] = base + 3;
    for (int m = a.w + 1; m <= b.x; m++) g_S[m] = base + 4;
    for (int m = b.x + 1; m <= b.y; m++) g_S[m] = base + 5;
    for (int m = b.y + 1; m <= b.z; m++) g_S[m] = base + 6;
    for (int m = b.z + 1; m <= b.w; m++) g_S[m] = base + 7;
    if (base + 8 == NUM_PINS) {
        for (int m = b.w + 1; m <= NUM_NETS; m++) g_S[m] = NUM_PINS;
    }
    // signal dependent kernel: our g_S writes are done
    asm volatile("griddepcontrol.launch_dependents;");
}

// Block handles 128 consecutive nets (pins contiguous). CSR lookups give
// st/en and pinlo/pinhi with no atomics/barrier. x/y/dx/dy staged via 16B
// cp.async (SoA) OVERLAPPED with the in-block counting sort. Hot loops are
// smem-only; global fallback loops (zero trips normally) cover span>CAP.
__global__ void __launch_bounds__(TB, 10) per_net_kernel(
    const float* __restrict__ X,
    const float* __restrict__ Y,
    const float* __restrict__ DX,
    const float* __restrict__ DY,
    const float* __restrict__ W,
    float* __restrict__ out)
{
    __shared__ float SX[CAP], SY[CAP], SDX[CAP], SDY[CAP];
    __shared__ int s_sst[NETS_PER_BLOCK];
    __shared__ int s_sen[NETS_PER_BLOCK];
    __shared__ int s_net[NETS_PER_BLOCK];
    __shared__ int s_hist[32];
    __shared__ int s_offs[32];
    __shared__ float swarp[4];

    const int tid  = threadIdx.x;
    const int base = blockIdx.x * NETS_PER_BLOCK;

    if (tid < 32) s_hist[tid] = 0;

    // PDL: block is already resident; wait for csr's g_S writes to be visible.
    asm volatile("griddepcontrol.wait;" ::: "memory");

    // CSR lookups. pinlo/pinhi are the same address for all threads -> L1 broadcast.
    const int st0   = __ldg(g_S + base + tid);
    const int en0   = __ldg(g_S + base + tid + 1);
    const int pinlo = __ldg(g_S + base);
    const int pinhi = __ldg(g_S + base + NETS_PER_BLOCK);
    const int sz0   = en0 - st0;

    // 16B-aligned staging window [alo, alo + limF)
    const int alo  = pinlo & ~3;
    const int spanF = pinhi - alo;
    const int limF  = ((spanF + 3) & ~3) < CAP ? ((spanF + 3) & ~3) : CAP;

    // Issue async staging FIRST; it flies while we sort below.
    for (int i = tid * 4; i < limF; i += TB * 4) {
        const int g = alo + i;
        CPA16(smem_u32(&SX[i]),  X + g);
        CPA16(smem_u32(&SY[i]),  Y + g);
        CPA16(smem_u32(&SDX[i]), DX + g);
        CPA16(smem_u32(&SDY[i]), DY + g);
    }
    asm volatile("cp.async.commit_group;" ::: "memory");

    // ---- counting sort by size (bins 0..31), overlapped with the copies ----
    __syncthreads();   // s_hist zero-init visible
    const int bin  = sz0 < 31 ? sz0 : 31;
    const int rank = atomicAdd(&s_hist[bin], 1);
    __syncthreads();
    if (tid < 32) {
        int c = s_hist[tid];
        int v = c;
        #pragma unroll
        for (int off = 1; off < 32; off <<= 1) {
            int u = __shfl_up_sync(0xffffffffu, v, off);
            if (tid >= off) v += u;
        }
        s_offs[tid] = v - c;
    }
    __syncthreads();
    const int pos = s_offs[bin] + rank;
    s_sst[pos] = st0;
    s_sen[pos] = en0;
    s_net[pos] = tid;

    asm volatile("cp.async.wait_group 0;" ::: "memory");
    __syncthreads();   // staging + scatter both visible

    const int st  = s_sst[tid];
    const int en  = s_sen[tid];
    const int cnt = en - st;
    float contrib = 0.0f;

    // cnt==1 nets: wa_x = wa_y = 0 exactly -> wl = 0 -> contrib = 0. Skip.
    if (cnt > 1) {
        const float w = __ldg(W + base + s_net[tid]);   // overlaps the passes

        const int js  = st - alo;
        const int je  = en - alo;
        const int jeH = je < CAP ? je : CAP;     // hot (smem) upper bound
        const int jcS = js > CAP ? js : CAP;     // cold (global) lower bound

        // ---- Pass 1: max/min/sum ----
        float xmax = -3.402823466e38f, xmin = 3.402823466e38f;
        float ymax = -3.402823466e38f, ymin = 3.402823466e38f;
        u64 sum2 = pk2(0.0f, 0.0f);
        #pragma unroll 2
        for (int j = js; j < jeH; j++) {
            float px = SX[j], py = SY[j];
            xmax = fmaxf(xmax, px); xmin = fminf(xmin, px);
            ymax = fmaxf(ymax, py); ymin = fminf(ymin, py);
            u64 t; asm("mov.b64 %0, {%1,%2};" : "=l"(t) : "f"(px), "f"(py));
            ADD2(sum2, sum2, t);
        }
        for (int j = jcS; j < je; j++) {          // normally zero trips
            float px = __ldg(X + alo + j), py = __ldg(Y + alo + j);
            xmax = fmaxf(xmax, px); xmin = fminf(xmin, px);
            ymax = fmaxf(ymax, py); ymin = fminf(ymin, py);
            u64 t = pk2(px, py);
            ADD2(sum2, sum2, t);
        }
        float sumx, sumy; up2(sum2, sumx, sumy);

        const float fcnt = (float)cnt;
        const float rc   = __fdividef(1.0f, fcnt);
        const float cx   = sumx * rc;
        const float cy   = sumy * rc;

        // ---- Pass 2: packed WA sums + direction penalty ----
        const u64 g2    = pk2(GL, GL);
        const u64 ng2   = pk2(-GL, -GL);
        const u64 cmaxg = pk2(-xmax * GL, -ymax * GL);
        const u64 cming = pk2(xmin * GL, ymin * GL);
        const u64 c2    = pk2(cx, cy);
        const u64 none2 = pk2(-1.0f, -1.0f);
        const u64 onec  = pk2(1.0f, 1.0f);
        u64 se2  = pk2(0.f, 0.f), sve2 = pk2(0.f, 0.f);
        u64 sm2  = pk2(0.f, 0.f), svm2 = pk2(0.f, 0.f);
        float pen = 0.f;

        #pragma unroll 2
        for (int j = js; j < jeH; j++) {
            float px = SX[j],  py  = SY[j];
            float ddx = SDX[j], ddy = SDY[j];
            u64 t; asm("mov.b64 %0, {%1,%2};" : "=l"(t) : "f"(px), "f"(py));

            u64 argp, argm;
            FMA2(argp, t, g2,  cmaxg);
            FMA2(argm, t, ng2, cming);
            float apx, apy, amx, amy;
            up2(argp, apx, apy);
            up2(argm, amx, amy);
            u64 ep2 = pk2(ex2a(apx), ex2a(apy));
            u64 em2 = pk2(ex2a(amx), ex2a(amy));

            FMA2(se2,  ep2, onec, se2);
            FMA2(sve2, t,   ep2,  sve2);
            FMA2(sm2,  em2, onec, sm2);
            FMA2(svm2, t,   em2,  svm2);

            u64 dd2;
            FMA2(dd2, t, none2, c2);
            float dxp, dyp;
            up2(dd2, dxp, dyp);
            float r2  = fmaxf(fmaf(dxp, dxp, dyp * dyp), 1e-16f);
            float dot = fmaf(dxp, ddx, dyp * ddy);
            float c   = dot * rsqrtf(r2);
            pen += fmaxf(0.5f - c, 0.0f);
        }
        for (int j = jcS; j < je; j++) {          // normally zero trips
            float px = __ldg(X + alo + j),  py  = __ldg(Y + alo + j);
            float ddx = __ldg(DX + alo + j), ddy = __ldg(DY + alo + j);
            u64 t = pk2(px, py);

            u64 argp, argm;
            FMA2(argp, t, g2,  cmaxg);
            FMA2(argm, t, ng2, cming);
            float apx, apy, amx, amy;
            up2(argp, apx, apy);
            up2(argm, amx, amy);
            u64 ep2 = pk2(ex2a(apx), ex2a(apy));
            u64 em2 = pk2(ex2a(amx), ex2a(amy));

            FMA2(se2,  ep2, onec, se2);
            FMA2(sve2, t,   ep2,  sve2);
            FMA2(sm2,  em2, onec, sm2);
            FMA2(svm2, t,   em2,  svm2);

            u64 dd2;
            FMA2(dd2, t, none2, c2);
            float dxp, dyp;
            up2(dd2, dxp, dyp);
            float r2  = fmaxf(fmaf(dxp, dxp, dyp * dyp), 1e-16f);
            float dot = fmaf(dxp, ddx, dyp * ddy);
            float c   = dot * rsqrtf(r2);
            pen += fmaxf(0.5f - c, 0.0f);
        }

        float sex, sey, svex, svey, smx, smy, svmx, svmy;
        up2(se2, sex, sey);   up2(sve2, svex, svey);
        up2(sm2, smx, smy);   up2(svm2, svmx, svmy);

        // se/sm >= 1 always (max/min pin contributes exp(0)=1): no eps guards.
        float wax = __fdividef(svex, sex) - __fdividef(svmx, smx);
        float way = __fdividef(svey, sey) - __fdividef(svmy, smy);
        float wl  = fmaxf(wax + way, 0.0f);        // ALPHA == 1.0
        float wtheta = pen * rc;
        contrib = w * (1.0f + wtheta) * wl;        // net_mask == 1
    }

    // Block reduction -> one atomicAdd per block.
    float v = contrib;
    #pragma unroll
    for (int off = 16; off > 0; off >>= 1)
        v += __shfl_down_sync(0xffffffffu, v, off);

    const int lane = tid & 31;
    const int wid  = tid >> 5;
    if (lane == 0) swarp[wid] = v;
    __syncthreads();
    if (wid == 0) {
        v = (lane < 4) ? swarp[lane] : 0.0f;
        #pragma unroll
        for (int off = 2; off > 0; off >>= 1)
            v += __shfl_down_sync(0xffffffffu, v, off);
        if (lane == 0) atomicAdd(out, v);
    }
}

extern "C" void kernel_launch(void* const* d_in, const int* in_sizes, int n_in,
                              void* d_out, int out_size)
{
    const float* pos  = (const float*)d_in[0];   // 2*P floats: x then y
    const float* dirx = (const float*)d_in[1];
    const float* diry = (const float*)d_in[2];
    const float* w    = (const float*)d_in[3];
    const int*   seg  = (const int*)d_in[4];
    float* out = (float*)d_out;

    csr_kernel<<<(NUM_PINS / 8 + 255) / 256, 256>>>(seg, out);

    // PDL launch: per_net's blocks dispatch while csr finishes; the kernel
    // gates its g_S reads with griddepcontrol.wait.
    {
        cudaLaunchConfig_t cfg = {};
        cfg.gridDim  = dim3(NUM_NETS / NETS_PER_BLOCK);
        cfg.blockDim = dim3(TB);
        cudaLaunchAttribute attr[1];
        attr[0].id = cudaLaunchAttributeProgrammaticStreamSerialization;
        attr[0].val.programmaticStreamSerializationAllowed = 1;
        cfg.attrs = attr;
        cfg.numAttrs = 1;
        cudaLaunchKernelEx(&cfg, per_net_kernel,
                           pos, pos + NUM_PINS, dirx, diry, w, out);
    }
}